// round 16
// baseline (speedup 1.0000x reference)
#include <cuda_runtime.h>
#include <math.h>
#include <stdint.h>

#define NTOK 32768
#define NE   64
#define NKTOP 8

// ===========================================================================
// scratch (device globals: allocation-free)
// ===========================================================================
__device__ __align__(16) float g_xh [(size_t)NTOK * 1024];
__device__ __align__(16) float g_xl [(size_t)NTOK * 1024];
__device__ __align__(16) float g_h1h[(size_t)NTOK * 2048];
__device__ __align__(16) float g_h1l[(size_t)NTOK * 2048];
__device__ __align__(16) float g_h2h[(size_t)NTOK * 2048];
__device__ __align__(16) float g_h2l[(size_t)NTOK * 2048];
__device__ __align__(16) float g_w1h[(size_t)1024 * 2048];
__device__ __align__(16) float g_w1l[(size_t)1024 * 2048];
__device__ __align__(16) float g_w2h[(size_t)2048 * 2048];
__device__ __align__(16) float g_w2l[(size_t)2048 * 2048];
__device__ __align__(16) float g_wnh[(size_t)2048 * 2048];
__device__ __align__(16) float g_wnl[(size_t)2048 * 2048];
__device__ __align__(16) float g_w3h[(size_t)2048 * 1024];
__device__ __align__(16) float g_w3l[(size_t)2048 * 1024];
__device__ __align__(16) float g_h4 [(size_t)NTOK * 1024];
__device__ __align__(16) float g_logits [(size_t)NTOK * NE];
__device__ __align__(16) float g_nlogits[(size_t)NTOK * NE];

__device__ __forceinline__ float tf32r(float x) {
    uint32_t h;
    asm("cvt.rna.tf32.f32 %0, %1;" : "=r"(h) : "f"(x));
    return __uint_as_float(h);
}

// elementwise split: v -> (hi, lo)
__global__ void split_k(const float* __restrict__ v,
                        float* __restrict__ h, float* __restrict__ l, size_t n) {
    const size_t i0 = ((size_t)blockIdx.x * blockDim.x + threadIdx.x) * 4;
    if (i0 >= n) return;
    float4 x = *(const float4*)(v + i0);
    float4 hh, ll;
    hh.x = tf32r(x.x); ll.x = tf32r(x.x - hh.x);
    hh.y = tf32r(x.y); ll.y = tf32r(x.y - hh.y);
    hh.z = tf32r(x.z); ll.z = tf32r(x.z - hh.z);
    hh.w = tf32r(x.w); ll.w = tf32r(x.w - hh.w);
    *(float4*)(h + i0) = hh;
    *(float4*)(l + i0) = ll;
}

// ===========================================================================
// Pre-split tf32 MMA GEMM (M multiple of 128): C = relu(A @ W + bias)
// cp.async 3-stage, K-chunk 16, CTA 128x128, warp 32x64, 2 CTA/SM.
// MMAs emitted in nt-PAIRS: each accumulator revisited at distance 4.
// Per-accumulator product order unchanged (hh, hl, lh) -> bit-identical.
// ===========================================================================
#define A_ST 20
#define B_ST 136
#define A_HF (128 * A_ST)
#define B_HF (16 * B_ST)
#define STG_FL (2 * A_HF + 2 * B_HF)
#define STG_B  (STG_FL * 4)
#define NSTAGE 3
#define SMEM_BYTES (NSTAGE * STG_B)   // 113664 -> 2 CTA/SM

__device__ __forceinline__ void mma8(float* c, const uint32_t* a, const uint32_t* b) {
    asm volatile(
        "mma.sync.aligned.m16n8k8.row.col.f32.tf32.tf32.f32 "
        "{%0,%1,%2,%3}, {%4,%5,%6,%7}, {%8,%9}, {%0,%1,%2,%3};"
        : "+f"(c[0]), "+f"(c[1]), "+f"(c[2]), "+f"(c[3])
        : "r"(a[0]), "r"(a[1]), "r"(a[2]), "r"(a[3]), "r"(b[0]), "r"(b[1]));
}
__device__ __forceinline__ void cpa16(uint32_t saddr, const void* g) {
    asm volatile("cp.async.cg.shared.global [%0], [%1], 16;" :: "r"(saddr), "l"(g));
}

template <bool WRITE_SPLIT>
__global__ __launch_bounds__(256, 2)
void mm_ps(const float* __restrict__ Ahg, const float* __restrict__ Alg,
           const float* __restrict__ Bhg, const float* __restrict__ Blg,
           const float* __restrict__ bias,
           float* __restrict__ C, float* __restrict__ Cl,
           int K, int M)
{
    extern __shared__ __align__(16) float sm[];
    uint32_t sb;
    asm("{ .reg .u64 t; cvta.to.shared.u64 t, %1; cvt.u32.u64 %0, t; }"
        : "=r"(sb) : "l"(sm));

    const int tid  = threadIdx.x;
    const int lane = tid & 31;
    const int wid  = tid >> 5;
    const int row0 = blockIdx.y << 7;
    const int col0 = blockIdx.x << 7;
    const int wm   = (wid & 3) << 5;
    const int wn   = (wid >> 2) << 6;
    const int g    = lane >> 2;
    const int tig  = lane & 3;

    const int arow = tid >> 2;           // + 64*i
    const int aj   = (tid & 3) << 2;
    const int brow = tid >> 5;           // + 8*i
    const int bj   = (tid & 31) << 2;

    float c[2][8][4];
#pragma unroll
    for (int mt = 0; mt < 2; ++mt)
#pragma unroll
        for (int nt = 0; nt < 8; ++nt)
#pragma unroll
            for (int e = 0; e < 4; ++e) c[mt][nt][e] = 0.f;

    const int nk = K >> 4;

    auto issue_chunk = [&](int t) {
        const int kc = t << 4;
        const uint32_t base = sb + (t % NSTAGE) * STG_B;
#pragma unroll
        for (int i = 0; i < 2; ++i) {
            const size_t go = (size_t)(row0 + arow + 64 * i) * K + kc + aj;
            const uint32_t so = ((arow + 64 * i) * A_ST + aj) * 4;
            cpa16(base + so,            Ahg + go);
            cpa16(base + A_HF * 4 + so, Alg + go);
        }
#pragma unroll
        for (int i = 0; i < 2; ++i) {
            const size_t go = (size_t)(kc + brow + 8 * i) * M + col0 + bj;
            const uint32_t so = ((brow + 8 * i) * B_ST + bj) * 4;
            cpa16(base + 2 * A_HF * 4 + so,          Bhg + go);
            cpa16(base + (2 * A_HF + B_HF) * 4 + so, Blg + go);
        }
        asm volatile("cp.async.commit_group;" ::: "memory");
    };

    issue_chunk(0);
    issue_chunk(1);

    for (int t = 0; t < nk; ++t) {
        if (t < nk - 1)
            asm volatile("cp.async.wait_group 1;" ::: "memory");
        else
            asm volatile("cp.async.wait_group 0;" ::: "memory");
        __syncthreads();

        const float* Ah = sm + (t % NSTAGE) * STG_FL;
        const float* Al = Ah + A_HF;
        const float* Bh = Al + A_HF;
        const float* Bl = Bh + B_HF;

#pragma unroll
        for (int k8 = 0; k8 < 2; ++k8) {
            uint32_t ah[2][4], al[2][4];
#pragma unroll
            for (int mt = 0; mt < 2; ++mt) {
                const int o = (wm + mt * 16 + g) * A_ST + k8 * 8 + tig;
                ah[mt][0] = __float_as_uint(Ah[o]);
                ah[mt][1] = __float_as_uint(Ah[o + 8 * A_ST]);
                ah[mt][2] = __float_as_uint(Ah[o + 4]);
                ah[mt][3] = __float_as_uint(Ah[o + 8 * A_ST + 4]);
                al[mt][0] = __float_as_uint(Al[o]);
                al[mt][1] = __float_as_uint(Al[o + 8 * A_ST]);
                al[mt][2] = __float_as_uint(Al[o + 4]);
                al[mt][3] = __float_as_uint(Al[o + 8 * A_ST + 4]);
            }
#pragma unroll
            for (int p = 0; p < 4; ++p) {
                const int n0 = 2 * p, n1 = 2 * p + 1;
                const int o0 = (k8 * 8 + tig) * B_ST + wn + n0 * 8 + g;
                const int o1 = o0 + 8;
                uint32_t bh0[2], bl0[2], bh1[2], bl1[2];
                bh0[0] = __float_as_uint(Bh[o0]);
                bh0[1] = __float_as_uint(Bh[o0 + 4 * B_ST]);
                bl0[0] = __float_as_uint(Bl[o0]);
                bl0[1] = __float_as_uint(Bl[o0 + 4 * B_ST]);
                bh1[0] = __float_as_uint(Bh[o1]);
                bh1[1] = __float_as_uint(Bh[o1 + 4 * B_ST]);
                bl1[0] = __float_as_uint(Bl[o1]);
                bl1[1] = __float_as_uint(Bl[o1 + 4 * B_ST]);
                // each accumulator revisited at distance 4; order hh,hl,lh kept
                mma8(c[0][n0], ah[0], bh0);
                mma8(c[1][n0], ah[1], bh0);
                mma8(c[0][n1], ah[0], bh1);
                mma8(c[1][n1], ah[1], bh1);
                mma8(c[0][n0], ah[0], bl0);
                mma8(c[1][n0], ah[1], bl0);
                mma8(c[0][n1], ah[0], bl1);
                mma8(c[1][n1], ah[1], bl1);
                mma8(c[0][n0], al[0], bh0);
                mma8(c[1][n0], al[1], bh0);
                mma8(c[0][n1], al[0], bh1);
                mma8(c[1][n1], al[1], bh1);
            }
        }

        if (t + 2 < nk) issue_chunk(t + 2);
    }

    // epilogue: bias + ReLU; raw or split write
#pragma unroll
    for (int mt = 0; mt < 2; ++mt) {
        const int r = row0 + wm + mt * 16 + g;
#pragma unroll
        for (int nt = 0; nt < 8; ++nt) {
            const int cc = col0 + wn + nt * 8 + 2 * tig;
            const float b0 = bias[cc], b1 = bias[cc + 1];
            float d00 = fmaxf(c[mt][nt][0] + b0, 0.f);
            float d01 = fmaxf(c[mt][nt][1] + b1, 0.f);
            float d10 = fmaxf(c[mt][nt][2] + b0, 0.f);
            float d11 = fmaxf(c[mt][nt][3] + b1, 0.f);
            if (WRITE_SPLIT) {
                float2 h0, l0, h1v, l1v;
                h0.x = tf32r(d00); l0.x = tf32r(d00 - h0.x);
                h0.y = tf32r(d01); l0.y = tf32r(d01 - h0.y);
                h1v.x = tf32r(d10); l1v.x = tf32r(d10 - h1v.x);
                h1v.y = tf32r(d11); l1v.y = tf32r(d11 - h1v.y);
                *(float2*)(C  + (size_t)r * M + cc)       = h0;
                *(float2*)(Cl + (size_t)r * M + cc)       = l0;
                *(float2*)(C  + (size_t)(r + 8) * M + cc) = h1v;
                *(float2*)(Cl + (size_t)(r + 8) * M + cc) = l1v;
            } else {
                *(float2*)(C + (size_t)r * M + cc)       = make_float2(d00, d01);
                *(float2*)(C + (size_t)(r + 8) * M + cc) = make_float2(d10, d11);
            }
        }
    }
}

// ---------------------------------------------------------------------------
// Narrow fp32 GEMM: C[N,64] = A[N,K] @ B[K,64] + bias
// EXACT fp32 — feeds top-k ranking; must NOT use tf32 (R15 lesson).
// ---------------------------------------------------------------------------
__global__ __launch_bounds__(256)
void gemm64_bias_k(const float* __restrict__ A, const float* __restrict__ B,
                   const float* __restrict__ bias, float* __restrict__ C, int K)
{
    __shared__ __align__(16) float As[16][128];
    __shared__ __align__(16) float Bsm[16][64];

    const int tid  = threadIdx.x;
    const int row0 = blockIdx.x << 7;
    const int tx   = tid & 15;
    const int ty   = tid >> 4;
    const int aRow = tid >> 2;
    const int aCol = (tid & 3) << 2;
    const int bRow = tid >> 4;
    const int bCol = (tid & 15) << 2;

    float acc[8][4];
#pragma unroll
    for (int i = 0; i < 8; ++i)
#pragma unroll
        for (int j = 0; j < 4; ++j) acc[i][j] = 0.f;

    const int nk = K >> 4;
    for (int t = 0; t < nk; ++t) {
        const int k0 = t << 4;
        float4 a0 = *(const float4*)&A[(size_t)(row0 + aRow)      * K + k0 + aCol];
        float4 a1 = *(const float4*)&A[(size_t)(row0 + aRow + 64) * K + k0 + aCol];
        float4 b0 = *(const float4*)&B[(size_t)(k0 + bRow) * 64 + bCol];
        __syncthreads();
        As[aCol + 0][aRow]      = a0.x; As[aCol + 1][aRow]      = a0.y;
        As[aCol + 2][aRow]      = a0.z; As[aCol + 3][aRow]      = a0.w;
        As[aCol + 0][aRow + 64] = a1.x; As[aCol + 1][aRow + 64] = a1.y;
        As[aCol + 2][aRow + 64] = a1.z; As[aCol + 3][aRow + 64] = a1.w;
        *(float4*)&Bsm[bRow][bCol] = b0;
        __syncthreads();
#pragma unroll
        for (int k = 0; k < 16; ++k) {
            float4 av0 = *(const float4*)&As[k][ty * 8];
            float4 av1 = *(const float4*)&As[k][ty * 8 + 4];
            float4 bv  = *(const float4*)&Bsm[k][tx * 4];
            float a[8] = {av0.x, av0.y, av0.z, av0.w, av1.x, av1.y, av1.z, av1.w};
            float b[4] = {bv.x, bv.y, bv.z, bv.w};
#pragma unroll
            for (int i = 0; i < 8; ++i)
#pragma unroll
                for (int j = 0; j < 4; ++j)
                    acc[i][j] = fmaf(a[i], b[j], acc[i][j]);
        }
    }
#pragma unroll
    for (int i = 0; i < 8; ++i) {
        const int r = row0 + ty * 8 + i;
        float4 v;
        v.x = acc[i][0] + bias[tx * 4 + 0];
        v.y = acc[i][1] + bias[tx * 4 + 1];
        v.z = acc[i][2] + bias[tx * 4 + 2];
        v.w = acc[i][3] + bias[tx * 4 + 3];
        *(float4*)&C[(size_t)r * 64 + tx * 4] = v;
    }
}

// ---------------------------------------------------------------------------
// Router: noisy logits, top-8 (lower index wins ties), masked softmax
// ---------------------------------------------------------------------------
__global__ void router_k(const float* __restrict__ logits,
                         const float* __restrict__ nlogits,
                         const float* __restrict__ noise,
                         float* __restrict__ probs,
                         float* __restrict__ idxOut)
{
    const int t = blockIdx.x * blockDim.x + threadIdx.x;
    if (t >= NTOK) return;

    const float* lg = logits  + (size_t)t * NE;
    const float* nl = nlogits + (size_t)t * NE;
    const float* nz = noise   + (size_t)t * NE;

    float v[NE];
#pragma unroll
    for (int e = 0; e < NE; ++e) {
        float xx = nl[e];
        float sp = fmaxf(xx, 0.f) + log1pf(expf(-fabsf(xx)));
        v[e] = lg[e] + nz[e] * sp;
    }

    int   bi[NKTOP];
    float bv[NKTOP];
#pragma unroll
    for (int j = 0; j < NKTOP; ++j) {
        float m = -INFINITY; int mi = 0;
        for (int e = 0; e < NE; ++e)
            if (v[e] > m) { m = v[e]; mi = e; }
        bv[j] = m; bi[j] = mi; v[mi] = -INFINITY;
    }

    const float mx = bv[0];
    float s = 0.f, ex[NKTOP];
#pragma unroll
    for (int j = 0; j < NKTOP; ++j) { ex[j] = expf(bv[j] - mx); s += ex[j]; }
    const float inv = 1.f / s;

    float o[NE];
#pragma unroll
    for (int e = 0; e < NE; ++e) o[e] = 0.f;
#pragma unroll
    for (int j = 0; j < NKTOP; ++j) o[bi[j]] = ex[j] * inv;

    float* op = probs + (size_t)t * NE;
#pragma unroll
    for (int e = 0; e < NE; e += 4)
        *(float4*)(op + e) = make_float4(o[e], o[e + 1], o[e + 2], o[e + 3]);

    if (idxOut)
#pragma unroll
        for (int j = 0; j < NKTOP; ++j)
            idxOut[(size_t)t * NKTOP + j] = (float)bi[j];
}

// ===========================================================================
extern "C" void kernel_launch(void* const* d_in, const int* in_sizes, int n_in,
                              void* d_out, int out_size)
{
    (void)in_sizes; (void)n_in;

    const float* x     = (const float*)d_in[0];
    const float* noise = (const float*)d_in[1];
    const float* w1    = (const float*)d_in[2];
    const float* b1    = (const float*)d_in[3];
    const float* w2    = (const float*)d_in[4];
    const float* b2    = (const float*)d_in[5];
    const float* wn    = (const float*)d_in[6];
    const float* bn    = (const float*)d_in[7];
    const float* w3    = (const float*)d_in[8];
    const float* b3    = (const float*)d_in[9];
    const float* w4    = (const float*)d_in[10];
    const float* b4    = (const float*)d_in[11];
    const float* wz    = (const float*)d_in[12];
    const float* bz    = (const float*)d_in[13];

    float *xh, *xl, *h1h, *h1l, *h2h, *h2l;
    float *w1h, *w1l, *w2h, *w2l, *wnh, *wnl, *w3h, *w3l;
    float *h4, *lgp, *nlp;
    cudaGetSymbolAddress((void**)&xh,  g_xh);
    cudaGetSymbolAddress((void**)&xl,  g_xl);
    cudaGetSymbolAddress((void**)&h1h, g_h1h);
    cudaGetSymbolAddress((void**)&h1l, g_h1l);
    cudaGetSymbolAddress((void**)&h2h, g_h2h);
    cudaGetSymbolAddress((void**)&h2l, g_h2l);
    cudaGetSymbolAddress((void**)&w1h, g_w1h);
    cudaGetSymbolAddress((void**)&w1l, g_w1l);
    cudaGetSymbolAddress((void**)&w2h, g_w2h);
    cudaGetSymbolAddress((void**)&w2l, g_w2l);
    cudaGetSymbolAddress((void**)&wnh, g_wnh);
    cudaGetSymbolAddress((void**)&wnl, g_wnl);
    cudaGetSymbolAddress((void**)&w3h, g_w3h);
    cudaGetSymbolAddress((void**)&w3l, g_w3l);
    cudaGetSymbolAddress((void**)&h4,  g_h4);
    cudaGetSymbolAddress((void**)&lgp, g_logits);
    cudaGetSymbolAddress((void**)&nlp, g_nlogits);

    cudaFuncSetAttribute(mm_ps<true>,  cudaFuncAttributeMaxDynamicSharedMemorySize, SMEM_BYTES);
    cudaFuncSetAttribute(mm_ps<false>, cudaFuncAttributeMaxDynamicSharedMemorySize, SMEM_BYTES);

    // ---- one-time splits ----
    const int st = 256;
    split_k<<<(NTOK * 1024 / 4 + st - 1) / st, st>>>(x,  xh,  xl,  (size_t)NTOK * 1024);
    split_k<<<(1024 * 2048 / 4 + st - 1) / st, st>>>(w1, w1h, w1l, (size_t)1024 * 2048);
    split_k<<<(2048 * 2048 / 4 + st - 1) / st, st>>>(w2, w2h, w2l, (size_t)2048 * 2048);
    split_k<<<(2048 * 2048 / 4 + st - 1) / st, st>>>(wn, wnh, wnl, (size_t)2048 * 2048);
    split_k<<<(2048 * 1024 / 4 + st - 1) / st, st>>>(w3, w3h, w3l, (size_t)2048 * 1024);

    const dim3 blk(256);
    // h1 = relu(x @ w1 + b1)   [32768, 2048], split output
    mm_ps<true><<<dim3(16, NTOK / 128), blk, SMEM_BYTES>>>(
        xh, xl, w1h, w1l, b1, h1h, h1l, 1024, 2048);
    // h2 = relu(h1 @ w2 + b2)  [32768, 2048], split output
    mm_ps<true><<<dim3(16, NTOK / 128), blk, SMEM_BYTES>>>(
        h1h, h1l, w2h, w2l, b2, h2h, h2l, 2048, 2048);
    // h1 = relu(h2 @ wn + bn)  [32768, 2048], split output (reuse h1 bufs)
    mm_ps<true><<<dim3(16, NTOK / 128), blk, SMEM_BYTES>>>(
        h2h, h2l, wnh, wnl, bn, h1h, h1l, 2048, 2048);
    // h4 = relu(h1 @ w3 + b3)  [32768, 1024], RAW fp32 output (feeds ranking)
    mm_ps<false><<<dim3(8, NTOK / 128), blk, SMEM_BYTES>>>(
        h1h, h1l, w3h, w3l, b3, h4, nullptr, 2048, 1024);

    // expert logits: EXACT fp32 (top-k inputs; tf32 here flips indices)
    gemm64_bias_k<<<NTOK / 128, 256>>>(h4, w4, b4, lgp, 1024);
    gemm64_bias_k<<<NTOK / 128, 256>>>(x,  wz, bz, nlp, 1024);

    float* probs  = (float*)d_out;
    float* idxOut = nullptr;
    if (out_size >= NTOK * NE + NTOK * NKTOP)
        idxOut = probs + (size_t)NTOK * NE;
    router_k<<<NTOK / 128, 128>>>(lgp, nlp, noise, probs, idxOut);
}

// round 17
// speedup vs baseline: 1.0319x; 1.0319x over previous
#include <cuda_runtime.h>
#include <math.h>
#include <stdint.h>

#define NTOK 32768
#define NE   64
#define NKTOP 8

// ===========================================================================
// scratch (device globals: allocation-free)
// ===========================================================================
__device__ __align__(16) float g_xh [(size_t)NTOK * 1024];
__device__ __align__(16) float g_xl [(size_t)NTOK * 1024];
__device__ __align__(16) float g_h1h[(size_t)NTOK * 2048];
__device__ __align__(16) float g_h1l[(size_t)NTOK * 2048];
__device__ __align__(16) float g_h2h[(size_t)NTOK * 2048];
__device__ __align__(16) float g_h2l[(size_t)NTOK * 2048];
__device__ __align__(16) float g_w1h[(size_t)1024 * 2048];
__device__ __align__(16) float g_w1l[(size_t)1024 * 2048];
__device__ __align__(16) float g_w2h[(size_t)2048 * 2048];
__device__ __align__(16) float g_w2l[(size_t)2048 * 2048];
__device__ __align__(16) float g_wnh[(size_t)2048 * 2048];
__device__ __align__(16) float g_wnl[(size_t)2048 * 2048];
__device__ __align__(16) float g_w3h[(size_t)2048 * 1024];
__device__ __align__(16) float g_w3l[(size_t)2048 * 1024];
__device__ __align__(16) float g_h4 [(size_t)NTOK * 1024];
__device__ __align__(16) float g_logits [(size_t)NTOK * NE];
__device__ __align__(16) float g_nlogits[(size_t)NTOK * NE];

__device__ __forceinline__ float tf32r(float x) {
    uint32_t h;
    asm("cvt.rna.tf32.f32 %0, %1;" : "=r"(h) : "f"(x));
    return __uint_as_float(h);
}

// elementwise split: v -> (hi, lo)
__global__ void split_k(const float* __restrict__ v,
                        float* __restrict__ h, float* __restrict__ l, size_t n) {
    const size_t i0 = ((size_t)blockIdx.x * blockDim.x + threadIdx.x) * 4;
    if (i0 >= n) return;
    float4 x = *(const float4*)(v + i0);
    float4 hh, ll;
    hh.x = tf32r(x.x); ll.x = tf32r(x.x - hh.x);
    hh.y = tf32r(x.y); ll.y = tf32r(x.y - hh.y);
    hh.z = tf32r(x.z); ll.z = tf32r(x.z - hh.z);
    hh.w = tf32r(x.w); ll.w = tf32r(x.w - hh.w);
    *(float4*)(h + i0) = hh;
    *(float4*)(l + i0) = ll;
}

// ===========================================================================
// Pre-split tf32 MMA GEMM (M multiple of 128): C = relu(A @ W + bias)
// cp.async 3-stage, K-chunk 16, CTA 128x128, warp 32x64, 2 CTA/SM.
// Inner ordering = the validated 11.01ms config (per-nt, 6 MMAs).
// ===========================================================================
#define A_ST 20
#define B_ST 136
#define A_HF (128 * A_ST)
#define B_HF (16 * B_ST)
#define STG_FL (2 * A_HF + 2 * B_HF)
#define STG_B  (STG_FL * 4)
#define NSTAGE 3
#define SMEM_BYTES (NSTAGE * STG_B)   // 113664 -> 2 CTA/SM

__device__ __forceinline__ void mma8(float* c, const uint32_t* a, const uint32_t* b) {
    asm volatile(
        "mma.sync.aligned.m16n8k8.row.col.f32.tf32.tf32.f32 "
        "{%0,%1,%2,%3}, {%4,%5,%6,%7}, {%8,%9}, {%0,%1,%2,%3};"
        : "+f"(c[0]), "+f"(c[1]), "+f"(c[2]), "+f"(c[3])
        : "r"(a[0]), "r"(a[1]), "r"(a[2]), "r"(a[3]), "r"(b[0]), "r"(b[1]));
}
__device__ __forceinline__ void cpa16(uint32_t saddr, const void* g) {
    asm volatile("cp.async.cg.shared.global [%0], [%1], 16;" :: "r"(saddr), "l"(g));
}

template <bool WRITE_SPLIT>
__global__ __launch_bounds__(256, 2)
void mm_ps(const float* __restrict__ Ahg, const float* __restrict__ Alg,
           const float* __restrict__ Bhg, const float* __restrict__ Blg,
           const float* __restrict__ bias,
           float* __restrict__ C, float* __restrict__ Cl,
           int K, int M)
{
    extern __shared__ __align__(16) float sm[];
    uint32_t sb;
    asm("{ .reg .u64 t; cvta.to.shared.u64 t, %1; cvt.u32.u64 %0, t; }"
        : "=r"(sb) : "l"(sm));

    const int tid  = threadIdx.x;
    const int lane = tid & 31;
    const int wid  = tid >> 5;
    const int row0 = blockIdx.y << 7;
    const int col0 = blockIdx.x << 7;
    const int wm   = (wid & 3) << 5;
    const int wn   = (wid >> 2) << 6;
    const int g    = lane >> 2;
    const int tig  = lane & 3;

    const int arow = tid >> 2;           // + 64*i
    const int aj   = (tid & 3) << 2;
    const int brow = tid >> 5;           // + 8*i
    const int bj   = (tid & 31) << 2;

    float c[2][8][4];
#pragma unroll
    for (int mt = 0; mt < 2; ++mt)
#pragma unroll
        for (int nt = 0; nt < 8; ++nt)
#pragma unroll
            for (int e = 0; e < 4; ++e) c[mt][nt][e] = 0.f;

    const int nk = K >> 4;

    auto issue_chunk = [&](int t) {
        const int kc = t << 4;
        const uint32_t base = sb + (t % NSTAGE) * STG_B;
#pragma unroll
        for (int i = 0; i < 2; ++i) {
            const size_t go = (size_t)(row0 + arow + 64 * i) * K + kc + aj;
            const uint32_t so = ((arow + 64 * i) * A_ST + aj) * 4;
            cpa16(base + so,            Ahg + go);
            cpa16(base + A_HF * 4 + so, Alg + go);
        }
#pragma unroll
        for (int i = 0; i < 2; ++i) {
            const size_t go = (size_t)(kc + brow + 8 * i) * M + col0 + bj;
            const uint32_t so = ((brow + 8 * i) * B_ST + bj) * 4;
            cpa16(base + 2 * A_HF * 4 + so,          Bhg + go);
            cpa16(base + (2 * A_HF + B_HF) * 4 + so, Blg + go);
        }
        asm volatile("cp.async.commit_group;" ::: "memory");
    };

    issue_chunk(0);
    issue_chunk(1);

    for (int t = 0; t < nk; ++t) {
        if (t < nk - 1)
            asm volatile("cp.async.wait_group 1;" ::: "memory");
        else
            asm volatile("cp.async.wait_group 0;" ::: "memory");
        __syncthreads();

        const float* Ah = sm + (t % NSTAGE) * STG_FL;
        const float* Al = Ah + A_HF;
        const float* Bh = Al + A_HF;
        const float* Bl = Bh + B_HF;

#pragma unroll
        for (int k8 = 0; k8 < 2; ++k8) {
            uint32_t ah[2][4], al[2][4];
#pragma unroll
            for (int mt = 0; mt < 2; ++mt) {
                const int o = (wm + mt * 16 + g) * A_ST + k8 * 8 + tig;
                ah[mt][0] = __float_as_uint(Ah[o]);
                ah[mt][1] = __float_as_uint(Ah[o + 8 * A_ST]);
                ah[mt][2] = __float_as_uint(Ah[o + 4]);
                ah[mt][3] = __float_as_uint(Ah[o + 8 * A_ST + 4]);
                al[mt][0] = __float_as_uint(Al[o]);
                al[mt][1] = __float_as_uint(Al[o + 8 * A_ST]);
                al[mt][2] = __float_as_uint(Al[o + 4]);
                al[mt][3] = __float_as_uint(Al[o + 8 * A_ST + 4]);
            }
#pragma unroll
            for (int nt = 0; nt < 8; ++nt) {
                const int o = (k8 * 8 + tig) * B_ST + wn + nt * 8 + g;
                uint32_t bh[2], bl[2];
                bh[0] = __float_as_uint(Bh[o]);
                bh[1] = __float_as_uint(Bh[o + 4 * B_ST]);
                bl[0] = __float_as_uint(Bl[o]);
                bl[1] = __float_as_uint(Bl[o + 4 * B_ST]);
                mma8(c[0][nt], ah[0], bh);
                mma8(c[1][nt], ah[1], bh);
                mma8(c[0][nt], ah[0], bl);
                mma8(c[1][nt], ah[1], bl);
                mma8(c[0][nt], al[0], bh);
                mma8(c[1][nt], al[1], bh);
            }
        }

        if (t + 2 < nk) issue_chunk(t + 2);
    }

    // epilogue: bias + ReLU; raw or split write
#pragma unroll
    for (int mt = 0; mt < 2; ++mt) {
        const int r = row0 + wm + mt * 16 + g;
#pragma unroll
        for (int nt = 0; nt < 8; ++nt) {
            const int cc = col0 + wn + nt * 8 + 2 * tig;
            const float b0 = bias[cc], b1 = bias[cc + 1];
            float d00 = fmaxf(c[mt][nt][0] + b0, 0.f);
            float d01 = fmaxf(c[mt][nt][1] + b1, 0.f);
            float d10 = fmaxf(c[mt][nt][2] + b0, 0.f);
            float d11 = fmaxf(c[mt][nt][3] + b1, 0.f);
            if (WRITE_SPLIT) {
                float2 h0, l0, h1v, l1v;
                h0.x = tf32r(d00); l0.x = tf32r(d00 - h0.x);
                h0.y = tf32r(d01); l0.y = tf32r(d01 - h0.y);
                h1v.x = tf32r(d10); l1v.x = tf32r(d10 - h1v.x);
                h1v.y = tf32r(d11); l1v.y = tf32r(d11 - h1v.y);
                *(float2*)(C  + (size_t)r * M + cc)       = h0;
                *(float2*)(Cl + (size_t)r * M + cc)       = l0;
                *(float2*)(C  + (size_t)(r + 8) * M + cc) = h1v;
                *(float2*)(Cl + (size_t)(r + 8) * M + cc) = l1v;
            } else {
                *(float2*)(C + (size_t)r * M + cc)       = make_float2(d00, d01);
                *(float2*)(C + (size_t)(r + 8) * M + cc) = make_float2(d10, d11);
            }
        }
    }
}

// ---------------------------------------------------------------------------
// Merged narrow fp32 GEMMs: gridDim.y = 2
//   y=0: logits  = h4 @ w4 + b4
//   y=1: nlogits = x  @ wz + bz
// EXACT fp32 — feeds top-k ranking; must NOT use tf32 (R15 lesson).
// Per-CTA math identical to the validated gemm64_bias_k.
// ---------------------------------------------------------------------------
__global__ __launch_bounds__(256)
void gemm64_dual_k(const float* __restrict__ A0, const float* __restrict__ A1,
                   const float* __restrict__ B0, const float* __restrict__ B1,
                   const float* __restrict__ bias0, const float* __restrict__ bias1,
                   float* __restrict__ C0, float* __restrict__ C1, int K)
{
    const float* A    = (blockIdx.y == 0) ? A0 : A1;
    const float* B    = (blockIdx.y == 0) ? B0 : B1;
    const float* bias = (blockIdx.y == 0) ? bias0 : bias1;
    float*       C    = (blockIdx.y == 0) ? C0 : C1;

    __shared__ __align__(16) float As[16][128];
    __shared__ __align__(16) float Bsm[16][64];

    const int tid  = threadIdx.x;
    const int row0 = blockIdx.x << 7;
    const int tx   = tid & 15;
    const int ty   = tid >> 4;
    const int aRow = tid >> 2;
    const int aCol = (tid & 3) << 2;
    const int bRow = tid >> 4;
    const int bCol = (tid & 15) << 2;

    float acc[8][4];
#pragma unroll
    for (int i = 0; i < 8; ++i)
#pragma unroll
        for (int j = 0; j < 4; ++j) acc[i][j] = 0.f;

    const int nk = K >> 4;
    for (int t = 0; t < nk; ++t) {
        const int k0 = t << 4;
        float4 a0 = *(const float4*)&A[(size_t)(row0 + aRow)      * K + k0 + aCol];
        float4 a1 = *(const float4*)&A[(size_t)(row0 + aRow + 64) * K + k0 + aCol];
        float4 b0 = *(const float4*)&B[(size_t)(k0 + bRow) * 64 + bCol];
        __syncthreads();
        As[aCol + 0][aRow]      = a0.x; As[aCol + 1][aRow]      = a0.y;
        As[aCol + 2][aRow]      = a0.z; As[aCol + 3][aRow]      = a0.w;
        As[aCol + 0][aRow + 64] = a1.x; As[aCol + 1][aRow + 64] = a1.y;
        As[aCol + 2][aRow + 64] = a1.z; As[aCol + 3][aRow + 64] = a1.w;
        *(float4*)&Bsm[bRow][bCol] = b0;
        __syncthreads();
#pragma unroll
        for (int k = 0; k < 16; ++k) {
            float4 av0 = *(const float4*)&As[k][ty * 8];
            float4 av1 = *(const float4*)&As[k][ty * 8 + 4];
            float4 bv  = *(const float4*)&Bsm[k][tx * 4];
            float a[8] = {av0.x, av0.y, av0.z, av0.w, av1.x, av1.y, av1.z, av1.w};
            float b[4] = {bv.x, bv.y, bv.z, bv.w};
#pragma unroll
            for (int i = 0; i < 8; ++i)
#pragma unroll
                for (int j = 0; j < 4; ++j)
                    acc[i][j] = fmaf(a[i], b[j], acc[i][j]);
        }
    }
#pragma unroll
    for (int i = 0; i < 8; ++i) {
        const int r = row0 + ty * 8 + i;
        float4 v;
        v.x = acc[i][0] + bias[tx * 4 + 0];
        v.y = acc[i][1] + bias[tx * 4 + 1];
        v.z = acc[i][2] + bias[tx * 4 + 2];
        v.w = acc[i][3] + bias[tx * 4 + 3];
        *(float4*)&C[(size_t)r * 64 + tx * 4] = v;
    }
}

// ---------------------------------------------------------------------------
// Router: noisy logits, top-8 (lower index wins ties), masked softmax
// ---------------------------------------------------------------------------
__global__ void router_k(const float* __restrict__ logits,
                         const float* __restrict__ nlogits,
                         const float* __restrict__ noise,
                         float* __restrict__ probs,
                         float* __restrict__ idxOut)
{
    const int t = blockIdx.x * blockDim.x + threadIdx.x;
    if (t >= NTOK) return;

    const float* lg = logits  + (size_t)t * NE;
    const float* nl = nlogits + (size_t)t * NE;
    const float* nz = noise   + (size_t)t * NE;

    float v[NE];
#pragma unroll
    for (int e = 0; e < NE; ++e) {
        float xx = nl[e];
        float sp = fmaxf(xx, 0.f) + log1pf(expf(-fabsf(xx)));
        v[e] = lg[e] + nz[e] * sp;
    }

    int   bi[NKTOP];
    float bv[NKTOP];
#pragma unroll
    for (int j = 0; j < NKTOP; ++j) {
        float m = -INFINITY; int mi = 0;
        for (int e = 0; e < NE; ++e)
            if (v[e] > m) { m = v[e]; mi = e; }
        bv[j] = m; bi[j] = mi; v[mi] = -INFINITY;
    }

    const float mx = bv[0];
    float s = 0.f, ex[NKTOP];
#pragma unroll
    for (int j = 0; j < NKTOP; ++j) { ex[j] = expf(bv[j] - mx); s += ex[j]; }
    const float inv = 1.f / s;

    float o[NE];
#pragma unroll
    for (int e = 0; e < NE; ++e) o[e] = 0.f;
#pragma unroll
    for (int j = 0; j < NKTOP; ++j) o[bi[j]] = ex[j] * inv;

    float* op = probs + (size_t)t * NE;
#pragma unroll
    for (int e = 0; e < NE; e += 4)
        *(float4*)(op + e) = make_float4(o[e], o[e + 1], o[e + 2], o[e + 3]);

    if (idxOut)
#pragma unroll
        for (int j = 0; j < NKTOP; ++j)
            idxOut[(size_t)t * NKTOP + j] = (float)bi[j];
}

// ===========================================================================
extern "C" void kernel_launch(void* const* d_in, const int* in_sizes, int n_in,
                              void* d_out, int out_size)
{
    (void)in_sizes; (void)n_in;

    const float* x     = (const float*)d_in[0];
    const float* noise = (const float*)d_in[1];
    const float* w1    = (const float*)d_in[2];
    const float* b1    = (const float*)d_in[3];
    const float* w2    = (const float*)d_in[4];
    const float* b2    = (const float*)d_in[5];
    const float* wn    = (const float*)d_in[6];
    const float* bn    = (const float*)d_in[7];
    const float* w3    = (const float*)d_in[8];
    const float* b3    = (const float*)d_in[9];
    const float* w4    = (const float*)d_in[10];
    const float* b4    = (const float*)d_in[11];
    const float* wz    = (const float*)d_in[12];
    const float* bz    = (const float*)d_in[13];

    float *xh, *xl, *h1h, *h1l, *h2h, *h2l;
    float *w1h, *w1l, *w2h, *w2l, *wnh, *wnl, *w3h, *w3l;
    float *h4, *lgp, *nlp;
    cudaGetSymbolAddress((void**)&xh,  g_xh);
    cudaGetSymbolAddress((void**)&xl,  g_xl);
    cudaGetSymbolAddress((void**)&h1h, g_h1h);
    cudaGetSymbolAddress((void**)&h1l, g_h1l);
    cudaGetSymbolAddress((void**)&h2h, g_h2h);
    cudaGetSymbolAddress((void**)&h2l, g_h2l);
    cudaGetSymbolAddress((void**)&w1h, g_w1h);
    cudaGetSymbolAddress((void**)&w1l, g_w1l);
    cudaGetSymbolAddress((void**)&w2h, g_w2h);
    cudaGetSymbolAddress((void**)&w2l, g_w2l);
    cudaGetSymbolAddress((void**)&wnh, g_wnh);
    cudaGetSymbolAddress((void**)&wnl, g_wnl);
    cudaGetSymbolAddress((void**)&w3h, g_w3h);
    cudaGetSymbolAddress((void**)&w3l, g_w3l);
    cudaGetSymbolAddress((void**)&h4,  g_h4);
    cudaGetSymbolAddress((void**)&lgp, g_logits);
    cudaGetSymbolAddress((void**)&nlp, g_nlogits);

    cudaFuncSetAttribute(mm_ps<true>,  cudaFuncAttributeMaxDynamicSharedMemorySize, SMEM_BYTES);
    cudaFuncSetAttribute(mm_ps<false>, cudaFuncAttributeMaxDynamicSharedMemorySize, SMEM_BYTES);

    // ---- one-time splits ----
    const int st = 256;
    split_k<<<(NTOK * 1024 / 4 + st - 1) / st, st>>>(x,  xh,  xl,  (size_t)NTOK * 1024);
    split_k<<<(1024 * 2048 / 4 + st - 1) / st, st>>>(w1, w1h, w1l, (size_t)1024 * 2048);
    split_k<<<(2048 * 2048 / 4 + st - 1) / st, st>>>(w2, w2h, w2l, (size_t)2048 * 2048);
    split_k<<<(2048 * 2048 / 4 + st - 1) / st, st>>>(wn, wnh, wnl, (size_t)2048 * 2048);
    split_k<<<(2048 * 1024 / 4 + st - 1) / st, st>>>(w3, w3h, w3l, (size_t)2048 * 1024);

    const dim3 blk(256);
    // h1 = relu(x @ w1 + b1)   [32768, 2048], split output
    mm_ps<true><<<dim3(16, NTOK / 128), blk, SMEM_BYTES>>>(
        xh, xl, w1h, w1l, b1, h1h, h1l, 1024, 2048);
    // h2 = relu(h1 @ w2 + b2)  [32768, 2048], split output
    mm_ps<true><<<dim3(16, NTOK / 128), blk, SMEM_BYTES>>>(
        h1h, h1l, w2h, w2l, b2, h2h, h2l, 2048, 2048);
    // h1 = relu(h2 @ wn + bn)  [32768, 2048], split output (reuse h1 bufs)
    mm_ps<true><<<dim3(16, NTOK / 128), blk, SMEM_BYTES>>>(
        h2h, h2l, wnh, wnl, bn, h1h, h1l, 2048, 2048);
    // h4 = relu(h1 @ w3 + b3)  [32768, 1024], RAW fp32 output (feeds ranking)
    mm_ps<false><<<dim3(8, NTOK / 128), blk, SMEM_BYTES>>>(
        h1h, h1l, w3h, w3l, b3, h4, nullptr, 2048, 1024);

    // expert logits: both narrow GEMMs in ONE launch (exact fp32)
    gemm64_dual_k<<<dim3(NTOK / 128, 2), 256>>>(h4, x, w4, wz, b4, bz, lgp, nlp, 1024);

    float* probs  = (float*)d_out;
    float* idxOut = nullptr;
    if (out_size >= NTOK * NE + NTOK * NKTOP)
        idxOut = probs + (size_t)NTOK * NE;
    router_k<<<NTOK / 128, 128>>>(lgp, nlp, noise, probs, idxOut);
}